// round 12
// baseline (speedup 1.0000x reference)
#include <cuda_runtime.h>
#include <cuda_bf16.h>

// Problem constants
#define BB   4
#define NN   256
#define CHN  128
#define CIN  1024
#define HH   120
#define WW   160
#define HWSZ (HH * WW)          // 19200
#define SRC  256

// ---------------------------------------------------------------------------
// Scratch (single __device__ global, no allocations anywhere)
// ---------------------------------------------------------------------------
// layout (floats):
//   hmid    :  B*CH*N              = 131072
//   relmapT :  B*SRC*CH            = 131072   (transposed: [b][src][ch])
//   rel0    :  B*CH*H*W            = 9830400
//   rel1    :  9830400
//   imgA    :  9830400
//   im(tmp) :  9830400
//   rm      :  9830400
//   dep0    :  B*2CH*H*W           = 19660800
//   dep1    :  19660800
//   dm      :  19660800
static const size_t OFF_HMID   = 0;
static const size_t OFF_RELMAP = 131072;
static const size_t OFF_REL0   = 262144;
static const size_t OFF_REL1   = OFF_REL0 + 9830400;
static const size_t OFF_IMGA   = OFF_REL1 + 9830400;
static const size_t OFF_IM     = OFF_IMGA + 9830400;
static const size_t OFF_RM     = OFF_IM   + 9830400;
static const size_t OFF_DEP0   = OFF_RM   + 9830400;
static const size_t OFF_DEP1   = OFF_DEP0 + 19660800;
static const size_t OFF_DM     = OFF_DEP1 + 19660800;
static const size_t SCRATCH_FLOATS = OFF_DM + 19660800;   // 108,396,544 floats

__device__ float g_scratch[SCRATCH_FLOATS];

// ---------------------------------------------------------------------------
// rel_embedding GEMM 1: hmid[b,o,n] = relu(sum_c W1[o,c]*tf[b,c,n] + b1[o])
// grid (128, 4), block 256 (n)
// ---------------------------------------------------------------------------
__global__ void relgemm1(const float* __restrict__ tf,
                         const float* __restrict__ w1,
                         const float* __restrict__ b1,
                         float* __restrict__ hmid)
{
    const int n = threadIdx.x;                 // 0..255
    const int o = blockIdx.x;                  // 0..127
    const int b = blockIdx.y;                  // 0..3
    const float* tfb = tf + (size_t)b * CIN * NN + n;
    const float* wr  = w1 + (size_t)o * CIN;
    float a0 = 0.f, a1 = 0.f, a2 = 0.f, a3 = 0.f;
#pragma unroll 4
    for (int c = 0; c < CIN; c += 4) {
        a0 = fmaf(wr[c + 0], tfb[(size_t)(c + 0) * NN], a0);
        a1 = fmaf(wr[c + 1], tfb[(size_t)(c + 1) * NN], a1);
        a2 = fmaf(wr[c + 2], tfb[(size_t)(c + 2) * NN], a2);
        a3 = fmaf(wr[c + 3], tfb[(size_t)(c + 3) * NN], a3);
    }
    float acc = (a0 + a1) + (a2 + a3) + b1[o];
    hmid[((size_t)b * CHN + o) * NN + n] = fmaxf(acc, 0.f);
}

// ---------------------------------------------------------------------------
// rel_embedding GEMM 2 + transpose:
// relmapT[b,n,o] = sum_c W2[o,c]*hmid[b,c,n] + b2[o]
// grid (256, 4), block 128 (o)
// ---------------------------------------------------------------------------
__global__ void relgemm2(const float* __restrict__ hmid,
                         const float* __restrict__ w2,
                         const float* __restrict__ b2,
                         float* __restrict__ relmapT)
{
    const int o = threadIdx.x;                 // 0..127
    const int n = blockIdx.x;                  // 0..255
    const int b = blockIdx.y;
    const float* wr = w2 + (size_t)o * CHN;
    const float* hb = hmid + (size_t)b * CHN * NN + n;
    float acc = 0.f;
#pragma unroll 8
    for (int c = 0; c < CHN; ++c)
        acc = fmaf(wr[c], hb[(size_t)c * NN], acc);
    relmapT[((size_t)b * SRC + n) * CHN + o] = acc + b2[o];
}

// ---------------------------------------------------------------------------
// Box gather: rel[b,c,y,x] = sum over valid boxes containing (y,x) of
//             relmapT[b, idx(y,box), c]   (nearest-interp row index)
// grid (5, 120, 4) = (x-tile, y, b), block 128 (c)
// ---------------------------------------------------------------------------
__global__ void __launch_bounds__(128)
relgather(const float* __restrict__ relmapT,
          const int* __restrict__ bbox,
          float* __restrict__ rel)
{
    const int c  = threadIdx.x;
    const int x0 = blockIdx.x * 32;
    const int y  = blockIdx.y;
    const int b  = blockIdx.z;

    __shared__ int   sbox[NN * 8];
    __shared__ float sxp[128 * 33];

    for (int i = threadIdx.x; i < NN * 8; i += 128)
        sbox[i] = bbox[(size_t)b * NN * 8 + i];
    __syncthreads();

    float acc[32];
#pragma unroll
    for (int k = 0; k < 32; ++k) acc[k] = 0.f;

    const float* rmb = relmapT + (size_t)b * SRC * CHN;

    for (int j = 0; j < NN; ++j) {
        const int* bx = &sbox[j * 8];
        const int sx1 = bx[0] >> 1, sy1 = bx[1] >> 1, sx2 = bx[2] >> 1, sy2 = bx[3] >> 1;
        const int ox1 = bx[4] >> 1, oy1 = bx[5] >> 1, ox2 = bx[6] >> 1, oy2 = bx[7] >> 1;
        const int sh = sy2 - sy1, sw = sx2 - sx1;
        const int oh = oy2 - oy1, ow = ox2 - ox1;
        if (!((sh >= 5) && (sw >= 5) && (oh >= 5) && (ow >= 5))) continue;

        if (y >= sy1 && y < sy2) {
            int idx = ((y - sy1) * SRC) / max(sh, 1);
            idx = min(idx, SRC - 1);
            float v = rmb[(size_t)idx * CHN + c];
            int xa = max(sx1 - x0, 0);
            int xb = min(sx2 - x0, 32);
            for (int k = xa; k < xb; ++k) acc[k] += v;
        }
        if (y >= oy1 && y < oy2) {
            int idx = ((y - oy1) * SRC) / max(oh, 1);
            idx = min(idx, SRC - 1);
            float v = rmb[(size_t)idx * CHN + c];
            int xa = max(ox1 - x0, 0);
            int xb = min(ox2 - x0, 32);
            for (int k = xa; k < xb; ++k) acc[k] += v;
        }
    }

    // transpose through smem for coalesced global stores
#pragma unroll
    for (int k = 0; k < 32; ++k) sxp[c * 33 + k] = acc[k];
    __syncthreads();
    for (int e = threadIdx.x; e < 128 * 32; e += 128) {
        int cc = e >> 5, xx = e & 31;
        rel[(((size_t)b * CHN + cc) * HH + y) * WW + x0 + xx] = sxp[cc * 33 + xx];
    }
}

// ---------------------------------------------------------------------------
// dep0 = concat(img, rel) along channels
// ---------------------------------------------------------------------------
__global__ void concat_dep(const float* __restrict__ img,
                           const float* __restrict__ rel,
                           float* __restrict__ dep)
{
    const int HW4 = HWSZ / 4;                          // 4800
    int i = blockIdx.x * blockDim.x + threadIdx.x;
    if (i >= BB * 256 * HW4) return;
    int b = i / (256 * HW4);
    int r = i - b * 256 * HW4;
    int c = r / HW4;
    int p = r - c * HW4;
    float4 v = (c < CHN)
        ? reinterpret_cast<const float4*>(img)[((size_t)b * CHN + c) * HW4 + p]
        : reinterpret_cast<const float4*>(rel)[((size_t)b * CHN + (c - CHN)) * HW4 + p];
    reinterpret_cast<float4*>(dep)[i] = v;
}

// ---------------------------------------------------------------------------
// update: d = relu(s + 0.5*m)   (vectorized)
// ---------------------------------------------------------------------------
__global__ void upd_relu(const float4* __restrict__ s,
                         const float4* __restrict__ m,
                         float4* __restrict__ d, int n4)
{
    int i = blockIdx.x * blockDim.x + threadIdx.x;
    if (i >= n4) return;
    float4 a = s[i], mm = m[i], r;
    r.x = fmaxf(fmaf(0.5f, mm.x, a.x), 0.f);
    r.y = fmaxf(fmaf(0.5f, mm.y, a.y), 0.f);
    r.z = fmaxf(fmaf(0.5f, mm.z, a.z), 0.f);
    r.w = fmaxf(fmaf(0.5f, mm.w, a.w), 0.f);
    d[i] = r;
}

// ---------------------------------------------------------------------------
// Direct 3x3 SAME conv, fp32, NCHW.
// Block: 256 threads computes a (64 out-ch) x (8 y) x (32 x) output tile.
// Register tile per thread: 8 out-ch x 8 x-positions (1 row). Input chunk of
// 8 channels staged in SMEM (stride-35 rows -> conflict-free), weights staged
// in SMEM (warp-broadcast reads).
// MODE: 0 = set, 1 = accumulate (+= conv+bias), 2 = set + relu
// Weights: w points at filter-set base, layout [Cout][Cin][3][3].
// ---------------------------------------------------------------------------
template<int MODE>
__global__ void __launch_bounds__(256, 2)
conv3x3(const float* __restrict__ in, const float* __restrict__ w,
        const float* __restrict__ bias, float* __restrict__ out,
        int Cin, int Cout)
{
    __shared__ float in_s[8 * 350];      // 8 ch x 10 rows x (stride 35)
    __shared__ float w_s[64 * 72];       // 64 o x (8 c x 9)

    const int tid = threadIdx.x;
    const int bx  = blockIdx.x;          // 0..74
    const int x0  = (bx % 5) * 32;
    const int y0  = (bx / 5) * 8;
    const int o0  = blockIdx.y * 64;
    const int b   = blockIdx.z;

    const int cg  = tid >> 5;            // warp id = out-channel group (0..7)
    const int pg  = tid & 31;
    const int ty  = pg & 7;              // row within tile
    const int tx8 = (pg >> 3) << 3;      // x base within tile (0,8,16,24)

    float acc[8][8];
#pragma unroll
    for (int i = 0; i < 8; ++i)
#pragma unroll
        for (int j = 0; j < 8; ++j) acc[i][j] = 0.f;

    const int wOS = Cin * 9;
    const float* inb = in + (size_t)b * Cin * HWSZ;

    for (int cc = 0; cc < Cin; cc += 8) {
        __syncthreads();
        // stage input tile (with halo), zero-pad out of bounds
        for (int idx = tid; idx < 8 * 340; idx += 256) {
            int c  = idx / 340;
            int r  = idx - c * 340;
            int iy = r / 34;
            int ix = r - iy * 34;
            int gy = y0 + iy - 1;
            int gx = x0 + ix - 1;
            float v = 0.f;
            if ((unsigned)gy < (unsigned)HH && (unsigned)gx < (unsigned)WW)
                v = inb[(size_t)(cc + c) * HWSZ + gy * WW + gx];
            in_s[c * 350 + iy * 35 + ix] = v;
        }
        // stage weights: 64 o x 8 c x 9 (contiguous per o)
        for (int idx = tid; idx < 64 * 72; idx += 256) {
            int o = idx / 72;
            int r = idx - o * 72;
            w_s[idx] = w[(size_t)(o0 + o) * wOS + cc * 9 + r];
        }
        __syncthreads();

#pragma unroll
        for (int kc = 0; kc < 8; ++kc) {
            const float* wrow = &w_s[(cg * 8) * 72 + kc * 9];
#pragma unroll
            for (int ky = 0; ky < 3; ++ky) {
                float in_r[10];
#pragma unroll
                for (int i = 0; i < 10; ++i)
                    in_r[i] = in_s[kc * 350 + (ty + ky) * 35 + tx8 + i];
#pragma unroll
                for (int kx = 0; kx < 3; ++kx) {
                    float wv[8];
#pragma unroll
                    for (int to = 0; to < 8; ++to)
                        wv[to] = wrow[to * 72 + ky * 3 + kx];
#pragma unroll
                    for (int to = 0; to < 8; ++to)
#pragma unroll
                        for (int px = 0; px < 8; ++px)
                            acc[to][px] = fmaf(wv[to], in_r[px + kx], acc[to][px]);
                }
            }
        }
    }

    // epilogue
#pragma unroll
    for (int to = 0; to < 8; ++to) {
        int o = o0 + cg * 8 + to;
        float bv = bias[o];
        float* op = out + (((size_t)b * Cout + o) * HH + (y0 + ty)) * WW + x0 + tx8;
#pragma unroll
        for (int px = 0; px < 8; ++px) {
            float v = acc[to][px] + bv;
            if (MODE == 1) v += op[px];
            if (MODE == 2) v = fmaxf(v, 0.f);
            op[px] = v;
        }
    }
}

// ---------------------------------------------------------------------------
// Orchestration
// ---------------------------------------------------------------------------
extern "C" void kernel_launch(void* const* d_in, const int* in_sizes, int n_in,
                              void* d_out, int out_size)
{
    const float* ram   = (const float*)d_in[0];   // (B,128,H,W)
    const float* tf    = (const float*)d_in[1];   // (B,1024,256)
    const float* rw1   = (const float*)d_in[2];
    const float* rb1   = (const float*)d_in[3];
    const float* rw2   = (const float*)d_in[4];
    const float* rb2   = (const float*)d_in[5];
    const float* dmcw  = (const float*)d_in[6];   // (4,256,128,3,3)
    const float* dmcb  = (const float*)d_in[7];   // (4,256)
    const float* imw01 = (const float*)d_in[8];   // (2,128,256,3,3)
    const float* imb01 = (const float*)d_in[9];
    const float* imw23 = (const float*)d_in[10];  // (2,128,128,3,3)
    const float* imb23 = (const float*)d_in[11];
    const float* rmw01 = (const float*)d_in[12];
    const float* rmb01 = (const float*)d_in[13];
    const float* rmw23 = (const float*)d_in[14];
    const float* rmb23 = (const float*)d_in[15];
    const float* ew1   = (const float*)d_in[16];  // (128,256,3,3)
    const float* eb1   = (const float*)d_in[17];
    const float* ew2   = (const float*)d_in[18];  // (128,128,3,3)
    const float* eb2   = (const float*)d_in[19];
    const int*   bbox  = (const int*)d_in[20];    // (B,256,8) int32
    float* out = (float*)d_out;

    float* S = nullptr;
    cudaGetSymbolAddress((void**)&S, g_scratch);
    float* hmid    = S + OFF_HMID;
    float* relmapT = S + OFF_RELMAP;
    float* rel0    = S + OFF_REL0;
    float* rel1    = S + OFF_REL1;
    float* imgA    = S + OFF_IMGA;
    float* im      = S + OFF_IM;     // also reused as emb1 tmp
    float* rm      = S + OFF_RM;
    float* dep0    = S + OFF_DEP0;
    float* dep1    = S + OFF_DEP1;
    float* dm      = S + OFF_DM;

    // rel_embedding (two 1x1 convs as GEMMs), rel_map stored transposed
    relgemm1<<<dim3(128, 4), 256>>>(tf, rw1, rb1, hmid);
    relgemm2<<<dim3(256, 4), 128>>>(hmid, rw2, rb2, relmapT);

    // box gather -> rel0
    relgather<<<dim3(5, HH, BB), 128>>>(relmapT, bbox, rel0);

    // dep0 = concat(img, rel0)
    const int nD4 = BB * 256 * HWSZ / 4;   // 4,915,200
    const int nC4 = BB * CHN * HWSZ / 4;   // 2,457,600
    concat_dep<<<(nD4 + 255) / 256, 256>>>(ram, rel0, dep0);

    const size_t DMC_SET = 256 * 128 * 9;  // per-filter-set stride in dmc_w

    // ---- TriGraph iteration 0 (needs dep, img, rel updates) ----
    conv3x3<0><<<dim3(75, 4, BB), 256>>>(ram,  dmcw + 0 * DMC_SET, dmcb + 0 * 256, dm, 128, 256);
    conv3x3<1><<<dim3(75, 4, BB), 256>>>(rel0, dmcw + 2 * DMC_SET, dmcb + 2 * 256, dm, 128, 256);

    conv3x3<0><<<dim3(75, 2, BB), 256>>>(dep0, imw01, imb01, im, 256, 128);
    conv3x3<1><<<dim3(75, 2, BB), 256>>>(rel0, imw23, imb23, im, 128, 128);

    conv3x3<0><<<dim3(75, 2, BB), 256>>>(dep0, rmw01, rmb01, rm, 256, 128);
    conv3x3<1><<<dim3(75, 2, BB), 256>>>(ram,  rmw23, rmb23, rm, 128, 128);

    upd_relu<<<(nD4 + 255) / 256, 256>>>((const float4*)dep0, (const float4*)dm, (float4*)dep1, nD4);
    upd_relu<<<(nC4 + 255) / 256, 256>>>((const float4*)ram,  (const float4*)im, (float4*)imgA, nC4);
    upd_relu<<<(nC4 + 255) / 256, 256>>>((const float4*)rel0, (const float4*)rm, (float4*)rel1, nC4);

    // ---- TriGraph iteration 1 (only dep feeds the output embedding) ----
    conv3x3<0><<<dim3(75, 4, BB), 256>>>(imgA, dmcw + 1 * DMC_SET, dmcb + 1 * 256, dm, 128, 256);
    conv3x3<1><<<dim3(75, 4, BB), 256>>>(rel1, dmcw + 3 * DMC_SET, dmcb + 3 * 256, dm, 128, 256);
    upd_relu<<<(nD4 + 255) / 256, 256>>>((const float4*)dep1, (const float4*)dm, (float4*)dep0, nD4);

    // ---- final embedding: conv -> relu -> conv ----
    conv3x3<2><<<dim3(75, 2, BB), 256>>>(dep0, ew1, eb1, im,  256, 128);  // im reused as tmp
    conv3x3<0><<<dim3(75, 2, BB), 256>>>(im,   ew2, eb2, out, 128, 128);
}

// round 15
// speedup vs baseline: 3.4010x; 3.4010x over previous
#include <cuda_runtime.h>
#include <cstdint>

#define BB   4
#define CHN  128
#define CIN  1024
#define NN   256
#define HH   120
#define WW   160
#define HWSZ 19200
#define SRC  256

// ---------------- scratch offsets (floats) ----------------
#define F_HMID   0u
#define F_RMAP   131072u
#define F_IMG0   262144u
#define F_REL0   10092544u
#define F_IMG1   19922944u
#define F_REL1   29753344u
#define F_D1A    39583744u
#define F_D1B    49414144u
#define F_D2A    59244544u
#define F_D2B    69074944u
#define F_EMBT   78905344u
#define F_WDM0   88735744u
#define F_WDM1   89325568u
#define F_WIM    89915392u
#define F_WRM    90357760u
#define F_WE1    90800128u
#define F_WE2    91095040u
#define F_BDM0   91242496u
#define F_BDM1   91242752u
#define F_BIM    91243008u
#define F_BRM    91243136u
#define F_TOTAL  91243264u

static __device__ __align__(1024) float g_scratch[F_TOTAL];

__device__ __forceinline__ float tf32_rn(float x) {
    uint32_t r; asm("cvt.rn.tf32.f32 %0, %1;" : "=r"(r) : "f"(x));
    return __uint_as_float(r);
}

// m16n8k8 tf32 mma (sm_80+, allowed at family-common target)
__device__ __forceinline__ void mma8(float* c, float a0, float a1, float a2, float a3,
                                     float b0, float b1) {
    asm volatile("mma.sync.aligned.m16n8k8.row.col.f32.tf32.tf32.f32 "
                 "{%0,%1,%2,%3}, {%4,%5,%6,%7}, {%8,%9}, {%0,%1,%2,%3};"
                 : "+f"(c[0]), "+f"(c[1]), "+f"(c[2]), "+f"(c[3])
                 : "r"(__float_as_uint(a0)), "r"(__float_as_uint(a1)),
                   "r"(__float_as_uint(a2)), "r"(__float_as_uint(a3)),
                   "r"(__float_as_uint(b0)), "r"(__float_as_uint(b1)));
}

// ---------------- small kernels ----------------
__global__ void relgemm1(const float* __restrict__ tf, const float* __restrict__ w1,
                         const float* __restrict__ b1, float* __restrict__ hmid)
{
    const int n = threadIdx.x, o = blockIdx.x, b = blockIdx.y;
    const float* tfb = tf + (size_t)b * CIN * NN + n;
    const float* wr  = w1 + (size_t)o * CIN;
    float a0=0.f, a1=0.f, a2=0.f, a3=0.f;
#pragma unroll 4
    for (int c = 0; c < CIN; c += 4) {
        a0 = fmaf(wr[c+0], tfb[(size_t)(c+0)*NN], a0);
        a1 = fmaf(wr[c+1], tfb[(size_t)(c+1)*NN], a1);
        a2 = fmaf(wr[c+2], tfb[(size_t)(c+2)*NN], a2);
        a3 = fmaf(wr[c+3], tfb[(size_t)(c+3)*NN], a3);
    }
    hmid[((size_t)b*CHN + o)*NN + n] = fmaxf((a0+a1)+(a2+a3)+b1[o], 0.f);
}

__global__ void relgemm2(const float* __restrict__ hmid, const float* __restrict__ w2,
                         const float* __restrict__ b2, float* __restrict__ rmap)
{
    const int o = threadIdx.x, n = blockIdx.x, b = blockIdx.y;
    const float* wr = w2 + (size_t)o * CHN;
    const float* hb = hmid + (size_t)b * CHN * NN + n;
    float acc = 0.f;
#pragma unroll 8
    for (int c = 0; c < CHN; ++c) acc = fmaf(wr[c], hb[(size_t)c*NN], acc);
    rmap[((size_t)b*SRC + n)*CHN + o] = acc + b2[o];
}

// Box gather -> rel (NHWC). grid (5, 120, 4), block 128 (c)
__global__ void __launch_bounds__(128)
relgather(const float* __restrict__ rmap, const int* __restrict__ bbox,
          float* __restrict__ rel)
{
    const int c = threadIdx.x, x0 = blockIdx.x*32, y = blockIdx.y, b = blockIdx.z;
    __shared__ int   sbox[NN*8];
    __shared__ float sxp[128*33];
    for (int i = threadIdx.x; i < NN*8; i += 128) sbox[i] = bbox[(size_t)b*NN*8 + i];
    __syncthreads();
    float acc[32];
#pragma unroll
    for (int k = 0; k < 32; ++k) acc[k] = 0.f;
    const float* rmb = rmap + (size_t)b * SRC * CHN;
    for (int j = 0; j < NN; ++j) {
        const int* bx = &sbox[j*8];
        const int sx1=bx[0]>>1, sy1=bx[1]>>1, sx2=bx[2]>>1, sy2=bx[3]>>1;
        const int ox1=bx[4]>>1, oy1=bx[5]>>1, ox2=bx[6]>>1, oy2=bx[7]>>1;
        const int sh=sy2-sy1, sw=sx2-sx1, oh=oy2-oy1, ow=ox2-ox1;
        if (!((sh>=5)&&(sw>=5)&&(oh>=5)&&(ow>=5))) continue;
        if (y >= sy1 && y < sy2) {
            int idx = min(((y-sy1)*SRC)/max(sh,1), SRC-1);
            float v = rmb[(size_t)idx*CHN + c];
            int xa = max(sx1-x0,0), xb = min(sx2-x0,32);
            for (int k = xa; k < xb; ++k) acc[k] += v;
        }
        if (y >= oy1 && y < oy2) {
            int idx = min(((y-oy1)*SRC)/max(oh,1), SRC-1);
            float v = rmb[(size_t)idx*CHN + c];
            int xa = max(ox1-x0,0), xb = min(ox2-x0,32);
            for (int k = xa; k < xb; ++k) acc[k] += v;
        }
    }
#pragma unroll
    for (int k = 0; k < 32; ++k) sxp[c*33 + k] = acc[k];
    __syncthreads();
    for (int e = threadIdx.x; e < 128*32; e += 128) {
        int xx = e >> 7, cc = e & 127;
        rel[(((size_t)b*HH + y)*WW + x0 + xx)*CHN + cc] = sxp[cc*33 + xx];
    }
}

// NCHW -> NHWC (C=128). grid (600, 4, B), block (32,8)
__global__ void nchw2nhwc(const float* __restrict__ in, float* __restrict__ out)
{
    __shared__ float t[32][33];
    const int p0 = blockIdx.x*32, c0 = blockIdx.y*32, b = blockIdx.z;
    const int x = threadIdx.x, y = threadIdx.y;
    for (int i = y; i < 32; i += 8)
        t[i][x] = in[((size_t)b*CHN + c0 + i)*HWSZ + p0 + x];
    __syncthreads();
    for (int i = y; i < 32; i += 8)
        out[((size_t)b*HWSZ + p0 + i)*CHN + c0 + x] = t[x][i];
}

// weight reorder + tf32 RN rounding: [o][c][tap] -> dst[o][soff + (c>>7)*1152 + tap*128 + (c&127)]
__global__ void wreorder(const float* __restrict__ w, float* __restrict__ dst,
                         int Cin, int Ktot, int soff, int total)
{
    int i = blockIdx.x*256 + threadIdx.x;
    if (i >= total) return;
    int o = i / (Cin*9), r = i - o*(Cin*9), c = r/9, tap = r - c*9;
    dst[(size_t)o*Ktot + soff + (c>>7)*1152 + tap*128 + (c&127)] = tf32_rn(w[i]);
}

__global__ void biascomb(const float* __restrict__ a, const float* __restrict__ b,
                         float* __restrict__ d, int n)
{
    int i = blockIdx.x*128 + threadIdx.x;
    if (i < n) d[i] = a[i] + b[i];
}

// ---------------- tf32 mma.sync implicit-GEMM 3x3 conv ----------------
// CTA tile: M=128 spatial (8y x 16x) x N=128 out-ch. K = nsec*1152 sections,
// section s reads 128-ch NHWC buffer s0/s1/s2 with tap offsets (implicit im2col).
// 8 warps (2 M x 4 N), warp tile 64x32, m16n8k8 tf32 fragments.
// SMEM: A/B double-buffered 128x32 tiles, row stride 36 floats (frag-LDS
// conflict-free, 16B-aligned rows).
// EPI 0: out = relu(state + 0.5*(D+bias))  [NHWC]
// EPI 1: out = relu(D+bias)                [NHWC]
// EPI 2: out = D+bias                      [NCHW final]
#define AS_OFF  0
#define BS_OFF  9216
#define BI_OFF  18432
#define SMEMF   18560
#define SMEMB   (SMEMF*4)

template<int EPI, int NT>
__global__ void __launch_bounds__(256)
conv_mma(const float* __restrict__ s0, const float* __restrict__ s1,
         const float* __restrict__ s2, int nsec,
         const float* __restrict__ w, const float* __restrict__ bias,
         const float* __restrict__ stA, const float* __restrict__ stB,
         float* __restrict__ outA, float* __restrict__ outB)
{
    extern __shared__ float sm[];
    const int tid = threadIdx.x, lane = tid & 31, wid = tid >> 5;
    const int wm = wid >> 2, wn = wid & 3;          // 2 x 4 warp grid
    const int gq = lane >> 2, tg = lane & 3;
    const int x0 = blockIdx.x * 16, y0 = blockIdx.y * 8;
    const int b = blockIdx.z / NT, ntile = blockIdx.z % NT, n0 = ntile << 7;
    const int Ktot = nsec * 1152, nch = nsec * 36;
    const int r = tid >> 3, g = tid & 7;            // loader: row r (0..31), 16B granule g

    float* bs = sm + BI_OFF;
    if (tid < 128) bs[tid] = bias[n0 + tid];

    float acc[4][4][4];
#pragma unroll
    for (int m = 0; m < 4; ++m)
#pragma unroll
        for (int n = 0; n < 4; ++n)
#pragma unroll
            for (int k = 0; k < 4; ++k) acc[m][n][k] = 0.f;

    float4 sA[4], sB[4];

    auto gload = [&](int ch) {
        const int sec = ch / 36, cs = ch - sec * 36;
        const int koff = cs * 32;
        const int tap = koff >> 7, c0k = koff & 127;
        const float* src = sec == 0 ? s0 : (sec == 1 ? s1 : s2);
        const int dy = tap / 3 - 1, dx = tap - (tap / 3) * 3 - 1;
        const int gx = x0 + (r & 15) + dx;
        const bool vx = (unsigned)gx < (unsigned)WW;
#pragma unroll
        for (int s = 0; s < 4; ++s) {
            const int gy = y0 + s * 2 + (r >> 4) + dy;   // p = s*32 + r
            float4 v = make_float4(0.f, 0.f, 0.f, 0.f);
            if (vx && (unsigned)gy < (unsigned)HH)
                v = *(const float4*)(src + (((size_t)b*HH + gy)*WW + gx)*128 + c0k + g*4);
            v.x = tf32_rn(v.x); v.y = tf32_rn(v.y); v.z = tf32_rn(v.z); v.w = tf32_rn(v.w);
            sA[s] = v;
        }
        const int kb = ch * 32;
#pragma unroll
        for (int s = 0; s < 4; ++s)
            sB[s] = *(const float4*)(w + (size_t)(n0 + s*32 + r)*Ktot + kb + g*4);
    };
    auto sts = [&](int buf) {
        float* A  = sm + AS_OFF + buf * 4608;
        float* Bp = sm + BS_OFF + buf * 4608;
#pragma unroll
        for (int s = 0; s < 4; ++s) {
            *(float4*)(A  + (s*32 + r)*36 + g*4) = sA[s];
            *(float4*)(Bp + (s*32 + r)*36 + g*4) = sB[s];
        }
    };
    auto compute = [&](int buf) {
        const float* A  = sm + AS_OFF + buf * 4608;
        const float* Bp = sm + BS_OFF + buf * 4608;
#pragma unroll
        for (int ks = 0; ks < 4; ++ks) {
            const int kk = ks * 8;
            float bf0[4], bf1[4];
#pragma unroll
            for (int n = 0; n < 4; ++n) {
                const int rb = wn*32 + n*8 + gq;
                bf0[n] = Bp[rb*36 + kk + tg];
                bf1[n] = Bp[rb*36 + kk + tg + 4];
            }
#pragma unroll
            for (int m = 0; m < 4; ++m) {
                const int ra = wm*64 + m*16 + gq;
                const float a0 = A[ra*36 + kk + tg];
                const float a1 = A[(ra+8)*36 + kk + tg];
                const float a2 = A[ra*36 + kk + tg + 4];
                const float a3 = A[(ra+8)*36 + kk + tg + 4];
#pragma unroll
                for (int n = 0; n < 4; ++n)
                    mma8(acc[m][n], a0, a1, a2, a3, bf0[n], bf1[n]);
            }
        }
    };

    gload(0);
    sts(0);
    __syncthreads();
    for (int ch = 0; ch < nch; ++ch) {
        if (ch + 1 < nch) gload(ch + 1);
        compute(ch & 1);
        if (ch + 1 < nch) sts((ch + 1) & 1);
        __syncthreads();
    }

    // ---- epilogue ----
    const float* st = (NT == 2 && ntile) ? stB : stA;
    float* op = (NT == 2 && ntile) ? outB : outA;
#pragma unroll
    for (int m = 0; m < 4; ++m) {
        const int prow = wm*64 + m*16 + gq;
#pragma unroll
        for (int h = 0; h < 2; ++h) {
            const int p = prow + h*8;
            const int gy = y0 + (p >> 4), gx2 = x0 + (p & 15);
#pragma unroll
            for (int n = 0; n < 4; ++n) {
                const int l = wn*32 + n*8 + tg*2;
                float d0 = acc[m][n][h*2+0] + bs[l];
                float d1 = acc[m][n][h*2+1] + bs[l+1];
                if (EPI == 0) {
                    const size_t base = (((size_t)b*HH + gy)*WW + gx2)*128 + l;
                    float2 sv = *(const float2*)(st + base);
                    d0 = fmaxf(fmaf(0.5f, d0, sv.x), 0.f);
                    d1 = fmaxf(fmaf(0.5f, d1, sv.y), 0.f);
                    *(float2*)(op + base) = make_float2(d0, d1);
                } else if (EPI == 1) {
                    const size_t base = (((size_t)b*HH + gy)*WW + gx2)*128 + l;
                    *(float2*)(op + base) = make_float2(fmaxf(d0, 0.f), fmaxf(d1, 0.f));
                } else {
                    op[((size_t)b*CHN + l    )*HWSZ + gy*WW + gx2] = d0;
                    op[((size_t)b*CHN + l + 1)*HWSZ + gy*WW + gx2] = d1;
                }
            }
        }
    }
}

// ---------------- orchestration ----------------
extern "C" void kernel_launch(void* const* d_in, const int* in_sizes, int n_in,
                              void* d_out, int out_size)
{
    const float* ram   = (const float*)d_in[0];
    const float* tf    = (const float*)d_in[1];
    const float* rw1   = (const float*)d_in[2];
    const float* rb1   = (const float*)d_in[3];
    const float* rw2   = (const float*)d_in[4];
    const float* rb2   = (const float*)d_in[5];
    const float* dmcw  = (const float*)d_in[6];
    const float* dmcb  = (const float*)d_in[7];
    const float* imw01 = (const float*)d_in[8];
    const float* imb01 = (const float*)d_in[9];
    const float* imw23 = (const float*)d_in[10];
    const float* imb23 = (const float*)d_in[11];
    const float* rmw01 = (const float*)d_in[12];
    const float* rmb01 = (const float*)d_in[13];
    const float* rmw23 = (const float*)d_in[14];
    const float* rmb23 = (const float*)d_in[15];
    const float* ew1   = (const float*)d_in[16];
    const float* eb1   = (const float*)d_in[17];
    const float* ew2   = (const float*)d_in[18];
    const float* eb2   = (const float*)d_in[19];
    const int*   bbox  = (const int*)d_in[20];
    float* out = (float*)d_out;

    float* S = nullptr;
    cudaGetSymbolAddress((void**)&S, g_scratch);
    float *hmid = S+F_HMID, *rmap = S+F_RMAP;
    float *img0 = S+F_IMG0, *rel0 = S+F_REL0, *img1 = S+F_IMG1, *rel1 = S+F_REL1;
    float *d1A = S+F_D1A, *d1B = S+F_D1B, *d2A = S+F_D2A, *d2B = S+F_D2B;
    float *embt = S+F_EMBT;
    float *wdm0 = S+F_WDM0, *wdm1 = S+F_WDM1, *wim = S+F_WIM, *wrm = S+F_WRM;
    float *we1 = S+F_WE1, *we2 = S+F_WE2;
    float *bdm0 = S+F_BDM0, *bdm1 = S+F_BDM1, *bim = S+F_BIM, *brm = S+F_BRM;

    cudaFuncSetAttribute(conv_mma<0,2>, cudaFuncAttributeMaxDynamicSharedMemorySize, SMEMB);
    cudaFuncSetAttribute(conv_mma<0,1>, cudaFuncAttributeMaxDynamicSharedMemorySize, SMEMB);
    cudaFuncSetAttribute(conv_mma<1,1>, cudaFuncAttributeMaxDynamicSharedMemorySize, SMEMB);
    cudaFuncSetAttribute(conv_mma<2,1>, cudaFuncAttributeMaxDynamicSharedMemorySize, SMEMB);

    const size_t DMC = 256*128*9;
    const int tDM = 256*128*9, tW = 128*256*9, tS = 128*128*9;

    // weight reorders (tap-major per 1152 section) + tf32 pre-rounding
    wreorder<<<(tDM+255)/256, 256>>>(dmcw + 0*DMC, wdm0, 128, 2304, 0,    tDM);
    wreorder<<<(tDM+255)/256, 256>>>(dmcw + 2*DMC, wdm0, 128, 2304, 1152, tDM);
    wreorder<<<(tDM+255)/256, 256>>>(dmcw + 1*DMC, wdm1, 128, 2304, 0,    tDM);
    wreorder<<<(tDM+255)/256, 256>>>(dmcw + 3*DMC, wdm1, 128, 2304, 1152, tDM);
    wreorder<<<(tW +255)/256, 256>>>(imw01,        wim,  256, 3456, 0,    tW);
    wreorder<<<(tS +255)/256, 256>>>(imw23,        wim,  128, 3456, 2304, tS);
    wreorder<<<(tW +255)/256, 256>>>(rmw01,        wrm,  256, 3456, 0,    tW);
    wreorder<<<(tS +255)/256, 256>>>(rmw23,        wrm,  128, 3456, 2304, tS);
    wreorder<<<(tW +255)/256, 256>>>(ew1,          we1,  256, 2304, 0,    tW);
    wreorder<<<(tS +255)/256, 256>>>(ew2,          we2,  128, 1152, 0,    tS);
    biascomb<<<2, 128>>>(dmcb + 0*256, dmcb + 2*256, bdm0, 256);
    biascomb<<<2, 128>>>(dmcb + 1*256, dmcb + 3*256, bdm1, 256);
    biascomb<<<1, 128>>>(imb01, imb23, bim, 128);
    biascomb<<<1, 128>>>(rmb01, rmb23, brm, 128);

    // rel embedding + box gather + layout transform
    relgemm1<<<dim3(128, 4), 256>>>(tf, rw1, rb1, hmid);
    relgemm2<<<dim3(256, 4), 128>>>(hmid, rw2, rb2, rmap);
    relgather<<<dim3(5, HH, BB), 128>>>(rmap, bbox, rel0);
    nchw2nhwc<<<dim3(600, 4, BB), dim3(32, 8)>>>(ram, img0);

    const dim3 G1(10, 15, BB), G2(10, 15, BB*2);
    // iter 0: dep1 = relu(concat(img0,rel0) + 0.5*(conv(img0,w0)+conv(rel0,w2)+b))
    conv_mma<0,2><<<G2, 256, SMEMB>>>(img0, rel0, nullptr, 2, wdm0, bdm0, img0, rel0, d1A, d1B);
    // img1 = relu(img0 + 0.5*(conv(dep0,w01)+conv(rel0,w23)))
    conv_mma<0,1><<<G1, 256, SMEMB>>>(img0, rel0, rel0, 3, wim, bim, img0, nullptr, img1, nullptr);
    // rel1 = relu(rel0 + 0.5*(conv(dep0,w01)+conv(img0,w23)))
    conv_mma<0,1><<<G1, 256, SMEMB>>>(img0, rel0, img0, 3, wrm, brm, rel0, nullptr, rel1, nullptr);
    // iter 1: dep2 = relu(dep1 + 0.5*(conv(img1,w1)+conv(rel1,w3)+b))
    conv_mma<0,2><<<G2, 256, SMEMB>>>(img1, rel1, nullptr, 2, wdm1, bdm1, d1A, d1B, d2A, d2B);
    // final embedding
    conv_mma<1,1><<<G1, 256, SMEMB>>>(d2A, d2B, nullptr, 2, we1, eb1, nullptr, nullptr, embt, nullptr);
    conv_mma<2,1><<<G1, 256, SMEMB>>>(embt, nullptr, nullptr, 1, we2, eb2, nullptr, nullptr, out, nullptr);
}

// round 16
// speedup vs baseline: 4.1696x; 1.2260x over previous
#include <cuda_runtime.h>
#include <cstdint>

#define BB   4
#define CHN  128
#define CIN  1024
#define NN   256
#define HH   120
#define WW   160
#define HWSZ 19200
#define SRC  256

// ---------------- scratch offsets (floats) ----------------
#define F_HMID   0u
#define F_RMAP   131072u
#define F_IMG0   262144u
#define F_REL0   10092544u
#define F_IMG1   19922944u
#define F_REL1   29753344u
#define F_D1A    39583744u
#define F_D1B    49414144u
#define F_D2A    59244544u
#define F_D2B    69074944u
#define F_EMBT   78905344u
#define F_WDM0   88735744u
#define F_WDM1   89325568u
#define F_WIM    89915392u
#define F_WRM    90357760u
#define F_WE1    90800128u
#define F_WE2    91095040u
#define F_BDM0   91242496u
#define F_BDM1   91242752u
#define F_BIM    91243008u
#define F_BRM    91243136u
#define F_TOTAL  91243264u

static __device__ __align__(1024) float g_scratch[F_TOTAL];

__device__ __forceinline__ float tf32_rn(float x) {
    uint32_t r; asm("cvt.rn.tf32.f32 %0, %1;" : "=r"(r) : "f"(x));
    return __uint_as_float(r);
}

// m16n8k8 tf32 mma (sm_80+, allowed at family-common target)
__device__ __forceinline__ void mma8(float* c, float a0, float a1, float a2, float a3,
                                     float b0, float b1) {
    asm volatile("mma.sync.aligned.m16n8k8.row.col.f32.tf32.tf32.f32 "
                 "{%0,%1,%2,%3}, {%4,%5,%6,%7}, {%8,%9}, {%0,%1,%2,%3};"
                 : "+f"(c[0]), "+f"(c[1]), "+f"(c[2]), "+f"(c[3])
                 : "r"(__float_as_uint(a0)), "r"(__float_as_uint(a1)),
                   "r"(__float_as_uint(a2)), "r"(__float_as_uint(a3)),
                   "r"(__float_as_uint(b0)), "r"(__float_as_uint(b1)));
}

// ---------------- small kernels ----------------
__global__ void relgemm1(const float* __restrict__ tf, const float* __restrict__ w1,
                         const float* __restrict__ b1, float* __restrict__ hmid)
{
    const int n = threadIdx.x, o = blockIdx.x, b = blockIdx.y;
    const float* tfb = tf + (size_t)b * CIN * NN + n;
    const float* wr  = w1 + (size_t)o * CIN;
    float a0=0.f, a1=0.f, a2=0.f, a3=0.f;
#pragma unroll 4
    for (int c = 0; c < CIN; c += 4) {
        a0 = fmaf(wr[c+0], tfb[(size_t)(c+0)*NN], a0);
        a1 = fmaf(wr[c+1], tfb[(size_t)(c+1)*NN], a1);
        a2 = fmaf(wr[c+2], tfb[(size_t)(c+2)*NN], a2);
        a3 = fmaf(wr[c+3], tfb[(size_t)(c+3)*NN], a3);
    }
    hmid[((size_t)b*CHN + o)*NN + n] = fmaxf((a0+a1)+(a2+a3)+b1[o], 0.f);
}

__global__ void relgemm2(const float* __restrict__ hmid, const float* __restrict__ w2,
                         const float* __restrict__ b2, float* __restrict__ rmap)
{
    const int o = threadIdx.x, n = blockIdx.x, b = blockIdx.y;
    const float* wr = w2 + (size_t)o * CHN;
    const float* hb = hmid + (size_t)b * CHN * NN + n;
    float acc = 0.f;
#pragma unroll 8
    for (int c = 0; c < CHN; ++c) acc = fmaf(wr[c], hb[(size_t)c*NN], acc);
    rmap[((size_t)b*SRC + n)*CHN + o] = acc + b2[o];
}

// Box gather -> rel (NHWC). grid (5, 120, 4), block 128 (c)
__global__ void __launch_bounds__(128)
relgather(const float* __restrict__ rmap, const int* __restrict__ bbox,
          float* __restrict__ rel)
{
    const int c = threadIdx.x, x0 = blockIdx.x*32, y = blockIdx.y, b = blockIdx.z;
    __shared__ int   sbox[NN*8];
    __shared__ float sxp[128*33];
    for (int i = threadIdx.x; i < NN*8; i += 128) sbox[i] = bbox[(size_t)b*NN*8 + i];
    __syncthreads();
    float acc[32];
#pragma unroll
    for (int k = 0; k < 32; ++k) acc[k] = 0.f;
    const float* rmb = rmap + (size_t)b * SRC * CHN;
    for (int j = 0; j < NN; ++j) {
        const int* bx = &sbox[j*8];
        const int sx1=bx[0]>>1, sy1=bx[1]>>1, sx2=bx[2]>>1, sy2=bx[3]>>1;
        const int ox1=bx[4]>>1, oy1=bx[5]>>1, ox2=bx[6]>>1, oy2=bx[7]>>1;
        const int sh=sy2-sy1, sw=sx2-sx1, oh=oy2-oy1, ow=ox2-ox1;
        if (!((sh>=5)&&(sw>=5)&&(oh>=5)&&(ow>=5))) continue;
        if (y >= sy1 && y < sy2) {
            int idx = min(((y-sy1)*SRC)/max(sh,1), SRC-1);
            float v = rmb[(size_t)idx*CHN + c];
            int xa = max(sx1-x0,0), xb = min(sx2-x0,32);
            for (int k = xa; k < xb; ++k) acc[k] += v;
        }
        if (y >= oy1 && y < oy2) {
            int idx = min(((y-oy1)*SRC)/max(oh,1), SRC-1);
            float v = rmb[(size_t)idx*CHN + c];
            int xa = max(ox1-x0,0), xb = min(ox2-x0,32);
            for (int k = xa; k < xb; ++k) acc[k] += v;
        }
    }
#pragma unroll
    for (int k = 0; k < 32; ++k) sxp[c*33 + k] = acc[k];
    __syncthreads();
    for (int e = threadIdx.x; e < 128*32; e += 128) {
        int xx = e >> 7, cc = e & 127;
        rel[(((size_t)b*HH + y)*WW + x0 + xx)*CHN + cc] = sxp[cc*33 + xx];
    }
}

// NCHW -> NHWC (C=128). grid (600, 4, B), block (32,8)
__global__ void nchw2nhwc(const float* __restrict__ in, float* __restrict__ out)
{
    __shared__ float t[32][33];
    const int p0 = blockIdx.x*32, c0 = blockIdx.y*32, b = blockIdx.z;
    const int x = threadIdx.x, y = threadIdx.y;
    for (int i = y; i < 32; i += 8)
        t[i][x] = in[((size_t)b*CHN + c0 + i)*HWSZ + p0 + x];
    __syncthreads();
    for (int i = y; i < 32; i += 8)
        out[((size_t)b*HWSZ + p0 + i)*CHN + c0 + x] = t[x][i];
}

// weight reorder + tf32 RN rounding. New K layout (channel-major within
// section): k = (c>>7)*1152 + ((c>>5)&3)*288 + tap*32 + (c&31)
__global__ void wreorder(const float* __restrict__ w, float* __restrict__ dst,
                         int Cin, int Ktot, int soff, int total)
{
    int i = blockIdx.x*256 + threadIdx.x;
    if (i >= total) return;
    int o = i / (Cin*9), rr = i - o*(Cin*9), c = rr/9, tap = rr - c*9;
    dst[(size_t)o*Ktot + soff + (c>>7)*1152 + ((c>>5)&3)*288 + tap*32 + (c&31)]
        = tf32_rn(w[i]);
}

__global__ void biascomb(const float* __restrict__ a, const float* __restrict__ b,
                         float* __restrict__ d, int n)
{
    int i = blockIdx.x*128 + threadIdx.x;
    if (i < n) d[i] = a[i] + b[i];
}

// ---------------- tf32 mma.sync implicit-GEMM 3x3 conv ----------------
// CTA tile: M=256 spatial (8y x 32x) x N=128 out-ch, 512 threads (16 warps,
// 4M x 4N grid, warp tile 64x32 of m16n8k8). K = nsec*1152 sections, each
// section reads one 128-ch NHWC buffer; K-order within section is
// channel-major (cblk*288 + tap*32 + c) so the 9 taps of one 32-ch slab hit
// L1 in consecutive chunks. Double-buffered SMEM (stride-36 rows).
// EPI 0: out = relu(state + 0.5*(D+bias))  [NHWC]
// EPI 1: out = relu(D+bias)                [NHWC]
// EPI 2: out = D+bias                      [NCHW final]
#define B_OFF   18432
#define BI_OFF  27648
#define SMEMF   27776
#define SMEMB   (SMEMF*4)

template<int EPI, int NT>
__global__ void __launch_bounds__(512, 1)
conv_mma(const float* __restrict__ s0, const float* __restrict__ s1,
         const float* __restrict__ s2, int nsec,
         const float* __restrict__ w, const float* __restrict__ bias,
         const float* __restrict__ stA, const float* __restrict__ stB,
         float* __restrict__ outA, float* __restrict__ outB)
{
    extern __shared__ float sm[];
    const int tid = threadIdx.x, lane = tid & 31, wid = tid >> 5;
    const int wm = wid >> 2, wn = wid & 3;          // 4 x 4 warp grid
    const int gq = lane >> 2, tg = lane & 3;
    const int x0 = blockIdx.x * 32, y0 = blockIdx.y * 8;
    const int b = blockIdx.z / NT, ntile = blockIdx.z % NT, n0 = ntile << 7;
    const int Ktot = nsec * 1152, nch = nsec * 36;
    const int r = tid >> 3, g = tid & 7;            // loader row r (0..63), 16B granule g

    float* bs = sm + BI_OFF;
    if (tid < 128) bs[tid] = bias[n0 + tid];

    float acc[4][4][4];
#pragma unroll
    for (int m = 0; m < 4; ++m)
#pragma unroll
        for (int n = 0; n < 4; ++n)
#pragma unroll
            for (int k = 0; k < 4; ++k) acc[m][n][k] = 0.f;

    float4 sA[4], sB[2];

    auto gload = [&](int ch) {
        const int sec = ch / 36, cs = ch - sec * 36;
        const int cblk = cs / 9, tap = cs - cblk * 9;
        const int c0k = cblk * 32;
        const float* src = sec == 0 ? s0 : (sec == 1 ? s1 : s2);
        const int dy = tap / 3 - 1, dx = tap - (tap / 3) * 3 - 1;
#pragma unroll
        for (int s = 0; s < 4; ++s) {
            const int p = s * 64 + r;                       // spatial row 0..255
            const int gy = y0 + (p >> 5) + dy;
            const int gx = x0 + (p & 31) + dx;
            float4 v = make_float4(0.f, 0.f, 0.f, 0.f);
            if ((unsigned)gy < (unsigned)HH && (unsigned)gx < (unsigned)WW)
                v = *(const float4*)(src + (((size_t)b*HH + gy)*WW + gx)*128 + c0k + g*4);
            v.x = tf32_rn(v.x); v.y = tf32_rn(v.y); v.z = tf32_rn(v.z); v.w = tf32_rn(v.w);
            sA[s] = v;
        }
        const int kb = ch * 32;
#pragma unroll
        for (int s = 0; s < 2; ++s)
            sB[s] = *(const float4*)(w + (size_t)(n0 + s*64 + r)*Ktot + kb + g*4);
    };
    auto sts = [&](int buf) {
        float* A  = sm + buf * 9216;
        float* Bp = sm + B_OFF + buf * 4608;
#pragma unroll
        for (int s = 0; s < 4; ++s)
            *(float4*)(A + (s*64 + r)*36 + g*4) = sA[s];
#pragma unroll
        for (int s = 0; s < 2; ++s)
            *(float4*)(Bp + (s*64 + r)*36 + g*4) = sB[s];
    };
    auto compute = [&](int buf) {
        const float* A  = sm + buf * 9216;
        const float* Bp = sm + B_OFF + buf * 4608;
#pragma unroll
        for (int ks = 0; ks < 4; ++ks) {
            const int kk = ks * 8;
            float bf0[4], bf1[4];
#pragma unroll
            for (int n = 0; n < 4; ++n) {
                const int rb = wn*32 + n*8 + gq;
                bf0[n] = Bp[rb*36 + kk + tg];
                bf1[n] = Bp[rb*36 + kk + tg + 4];
            }
#pragma unroll
            for (int m = 0; m < 4; ++m) {
                const int ra = wm*64 + m*16 + gq;
                const float a0 = A[ra*36 + kk + tg];
                const float a1 = A[(ra+8)*36 + kk + tg];
                const float a2 = A[ra*36 + kk + tg + 4];
                const float a3 = A[(ra+8)*36 + kk + tg + 4];
#pragma unroll
                for (int n = 0; n < 4; ++n)
                    mma8(acc[m][n], a0, a1, a2, a3, bf0[n], bf1[n]);
            }
        }
    };

    gload(0);
    sts(0);
    __syncthreads();
    for (int ch = 0; ch < nch; ++ch) {
        if (ch + 1 < nch) gload(ch + 1);
        compute(ch & 1);
        if (ch + 1 < nch) sts((ch + 1) & 1);
        __syncthreads();
    }

    // ---- epilogue ----
    const float* st = (NT == 2 && ntile) ? stB : stA;
    float* op = (NT == 2 && ntile) ? outB : outA;
#pragma unroll
    for (int m = 0; m < 4; ++m) {
        const int prow = wm*64 + m*16 + gq;
#pragma unroll
        for (int h = 0; h < 2; ++h) {
            const int p = prow + h*8;
            const int gy = y0 + (p >> 5), gx2 = x0 + (p & 31);
#pragma unroll
            for (int n = 0; n < 4; ++n) {
                const int l = wn*32 + n*8 + tg*2;
                float d0 = acc[m][n][h*2+0] + bs[l];
                float d1 = acc[m][n][h*2+1] + bs[l+1];
                if (EPI == 0) {
                    const size_t base = (((size_t)b*HH + gy)*WW + gx2)*128 + l;
                    float2 sv = *(const float2*)(st + base);
                    d0 = fmaxf(fmaf(0.5f, d0, sv.x), 0.f);
                    d1 = fmaxf(fmaf(0.5f, d1, sv.y), 0.f);
                    *(float2*)(op + base) = make_float2(d0, d1);
                } else if (EPI == 1) {
                    const size_t base = (((size_t)b*HH + gy)*WW + gx2)*128 + l;
                    *(float2*)(op + base) = make_float2(fmaxf(d0, 0.f), fmaxf(d1, 0.f));
                } else {
                    op[((size_t)b*CHN + l    )*HWSZ + gy*WW + gx2] = d0;
                    op[((size_t)b*CHN + l + 1)*HWSZ + gy*WW + gx2] = d1;
                }
            }
        }
    }
}

// ---------------- orchestration ----------------
extern "C" void kernel_launch(void* const* d_in, const int* in_sizes, int n_in,
                              void* d_out, int out_size)
{
    const float* ram   = (const float*)d_in[0];
    const float* tf    = (const float*)d_in[1];
    const float* rw1   = (const float*)d_in[2];
    const float* rb1   = (const float*)d_in[3];
    const float* rw2   = (const float*)d_in[4];
    const float* rb2   = (const float*)d_in[5];
    const float* dmcw  = (const float*)d_in[6];
    const float* dmcb  = (const float*)d_in[7];
    const float* imw01 = (const float*)d_in[8];
    const float* imb01 = (const float*)d_in[9];
    const float* imw23 = (const float*)d_in[10];
    const float* imb23 = (const float*)d_in[11];
    const float* rmw01 = (const float*)d_in[12];
    const float* rmb01 = (const float*)d_in[13];
    const float* rmw23 = (const float*)d_in[14];
    const float* rmb23 = (const float*)d_in[15];
    const float* ew1   = (const float*)d_in[16];
    const float* eb1   = (const float*)d_in[17];
    const float* ew2   = (const float*)d_in[18];
    const float* eb2   = (const float*)d_in[19];
    const int*   bbox  = (const int*)d_in[20];
    float* out = (float*)d_out;

    float* S = nullptr;
    cudaGetSymbolAddress((void**)&S, g_scratch);
    float *hmid = S+F_HMID, *rmap = S+F_RMAP;
    float *img0 = S+F_IMG0, *rel0 = S+F_REL0, *img1 = S+F_IMG1, *rel1 = S+F_REL1;
    float *d1A = S+F_D1A, *d1B = S+F_D1B, *d2A = S+F_D2A, *d2B = S+F_D2B;
    float *embt = S+F_EMBT;
    float *wdm0 = S+F_WDM0, *wdm1 = S+F_WDM1, *wim = S+F_WIM, *wrm = S+F_WRM;
    float *we1 = S+F_WE1, *we2 = S+F_WE2;
    float *bdm0 = S+F_BDM0, *bdm1 = S+F_BDM1, *bim = S+F_BIM, *brm = S+F_BRM;

    cudaFuncSetAttribute(conv_mma<0,2>, cudaFuncAttributeMaxDynamicSharedMemorySize, SMEMB);
    cudaFuncSetAttribute(conv_mma<0,1>, cudaFuncAttributeMaxDynamicSharedMemorySize, SMEMB);
    cudaFuncSetAttribute(conv_mma<1,1>, cudaFuncAttributeMaxDynamicSharedMemorySize, SMEMB);
    cudaFuncSetAttribute(conv_mma<2,1>, cudaFuncAttributeMaxDynamicSharedMemorySize, SMEMB);

    const size_t DMC = 256*128*9;
    const int tDM = 256*128*9, tW = 128*256*9, tS = 128*128*9;

    // weight reorders (channel-major K per 1152 section) + tf32 pre-rounding
    wreorder<<<(tDM+255)/256, 256>>>(dmcw + 0*DMC, wdm0, 128, 2304, 0,    tDM);
    wreorder<<<(tDM+255)/256, 256>>>(dmcw + 2*DMC, wdm0, 128, 2304, 1152, tDM);
    wreorder<<<(tDM+255)/256, 256>>>(dmcw + 1*DMC, wdm1, 128, 2304, 0,    tDM);
    wreorder<<<(tDM+255)/256, 256>>>(dmcw + 3*DMC, wdm1, 128, 2304, 1152, tDM);
    wreorder<<<(tW +255)/256, 256>>>(imw01,        wim,  256, 3456, 0,    tW);
    wreorder<<<(tS +255)/256, 256>>>(imw23,        wim,  128, 3456, 2304, tS);
    wreorder<<<(tW +255)/256, 256>>>(rmw01,        wrm,  256, 3456, 0,    tW);
    wreorder<<<(tS +255)/256, 256>>>(rmw23,        wrm,  128, 3456, 2304, tS);
    wreorder<<<(tW +255)/256, 256>>>(ew1,          we1,  256, 2304, 0,    tW);
    wreorder<<<(tS +255)/256, 256>>>(ew2,          we2,  128, 1152, 0,    tS);
    biascomb<<<2, 128>>>(dmcb + 0*256, dmcb + 2*256, bdm0, 256);
    biascomb<<<2, 128>>>(dmcb + 1*256, dmcb + 3*256, bdm1, 256);
    biascomb<<<1, 128>>>(imb01, imb23, bim, 128);
    biascomb<<<1, 128>>>(rmb01, rmb23, brm, 128);

    // rel embedding + box gather + layout transform
    relgemm1<<<dim3(128, 4), 256>>>(tf, rw1, rb1, hmid);
    relgemm2<<<dim3(256, 4), 128>>>(hmid, rw2, rb2, rmap);
    relgather<<<dim3(5, HH, BB), 128>>>(rmap, bbox, rel0);
    nchw2nhwc<<<dim3(600, 4, BB), dim3(32, 8)>>>(ram, img0);

    const dim3 G1(5, 15, BB), G2(5, 15, BB*2);
    // iter 0: dep1 = relu(concat(img0,rel0) + 0.5*(conv(img0,w0)+conv(rel0,w2)+b))
    conv_mma<0,2><<<G2, 512, SMEMB>>>(img0, rel0, nullptr, 2, wdm0, bdm0, img0, rel0, d1A, d1B);
    // img1 = relu(img0 + 0.5*(conv(dep0,w01)+conv(rel0,w23)))
    conv_mma<0,1><<<G1, 512, SMEMB>>>(img0, rel0, rel0, 3, wim, bim, img0, nullptr, img1, nullptr);
    // rel1 = relu(rel0 + 0.5*(conv(dep0,w01)+conv(img0,w23)))
    conv_mma<0,1><<<G1, 512, SMEMB>>>(img0, rel0, img0, 3, wrm, brm, rel0, nullptr, rel1, nullptr);
    // iter 1: dep2 = relu(dep1 + 0.5*(conv(img1,w1)+conv(rel1,w3)+b))
    conv_mma<0,2><<<G2, 512, SMEMB>>>(img1, rel1, nullptr, 2, wdm1, bdm1, d1A, d1B, d2A, d2B);
    // final embedding
    conv_mma<1,1><<<G1, 512, SMEMB>>>(d2A, d2B, nullptr, 2, we1, eb1, nullptr, nullptr, embt, nullptr);
    conv_mma<2,1><<<G1, 512, SMEMB>>>(embt, nullptr, nullptr, 1, we2, eb2, nullptr, nullptr, out, nullptr);
}